// round 1
// baseline (speedup 1.0000x reference)
#include <cuda_runtime.h>
#include <math.h>

// Problem constants
#define BATCH 2
#define SEQ   2048
#define DIM   2048
#define HEADS 32
#define DHEAD 64
#define ROWS  (BATCH * SEQ)          // 4096
#define DIM_INNER (HEADS * DHEAD)    // 2048

// ---------------- Scratch (static device globals — allocation-free) ----------
__device__ float g_xn[ROWS * DIM];          // 32 MB  rmsnorm(x)
__device__ float g_q [ROWS * DIM_INNER];    // 32 MB  q  [m, h*64+d]
__device__ float g_kv[ROWS * 2 * DIM_INNER];// 64 MB  k | v
__device__ float g_ao[ROWS * DIM_INNER];    // 32 MB  attention output

// ============================ RMSNorm ========================================
__global__ void rmsnorm_kernel(const float* __restrict__ x,
                               const float* __restrict__ gamma,
                               float* __restrict__ xn) {
    int row = blockIdx.x;
    const float* xr = x + (size_t)row * DIM;
    float ss = 0.f;
    for (int i = threadIdx.x; i < DIM; i += blockDim.x) {
        float v = xr[i];
        ss += v * v;
    }
    // block reduction
    __shared__ float red[32];
    int lane = threadIdx.x & 31, wid = threadIdx.x >> 5;
    #pragma unroll
    for (int off = 16; off > 0; off >>= 1) ss += __shfl_xor_sync(0xffffffffu, ss, off);
    if (lane == 0) red[wid] = ss;
    __syncthreads();
    if (wid == 0) {
        float v = (lane < (blockDim.x >> 5)) ? red[lane] : 0.f;
        #pragma unroll
        for (int off = 16; off > 0; off >>= 1) v += __shfl_xor_sync(0xffffffffu, v, off);
        if (lane == 0) red[0] = v;
    }
    __syncthreads();
    float norm = sqrtf(red[0]);
    float s = sqrtf((float)DIM) / fmaxf(norm, 1e-12f);
    float* xo = xn + (size_t)row * DIM;
    for (int i = threadIdx.x; i < DIM; i += blockDim.x)
        xo[i] = xr[i] * s * gamma[i];
}

// ============================ SGEMM (fp32) ===================================
// C[M,N] = A[M,K] @ B[K,N], all row-major, dims divisible by tile sizes.
#define GBM 128
#define GBN 128
#define GBK 8
#define GTM 8
#define GTN 8

__global__ void __launch_bounds__(256, 2)
sgemm_kernel(const float* __restrict__ A, const float* __restrict__ B,
             float* __restrict__ C, int M, int N, int K) {
    __shared__ float As[GBK][GBM];
    __shared__ float Bs[GBK][GBN];

    int brow = blockIdx.y * GBM;
    int bcol = blockIdx.x * GBN;
    int tid  = threadIdx.x;

    // A: 128 rows x 8 k → 256 float4 (2 per row)
    int a_row  = tid >> 1;
    int a_col4 = (tid & 1) << 2;
    // B: 8 k x 128 cols → 256 float4 (32 per k-row)
    int b_row  = tid >> 5;
    int b_col4 = (tid & 31) << 2;

    int ty = tid >> 4, tx = tid & 15;

    float acc[GTM][GTN];
    #pragma unroll
    for (int i = 0; i < GTM; i++)
        #pragma unroll
        for (int j = 0; j < GTN; j++) acc[i][j] = 0.f;

    const float* Aptr = A + (size_t)(brow + a_row) * K + a_col4;
    const float* Bptr = B + (size_t)b_row * N + bcol + b_col4;

    for (int k0 = 0; k0 < K; k0 += GBK) {
        float4 a4 = *(const float4*)(Aptr + k0);
        As[a_col4 + 0][a_row] = a4.x;
        As[a_col4 + 1][a_row] = a4.y;
        As[a_col4 + 2][a_row] = a4.z;
        As[a_col4 + 3][a_row] = a4.w;
        float4 b4 = *(const float4*)(Bptr + (size_t)k0 * N);
        *(float4*)&Bs[b_row][b_col4] = b4;
        __syncthreads();

        #pragma unroll
        for (int k = 0; k < GBK; k++) {
            float ra[GTM], rb[GTN];
            #pragma unroll
            for (int i = 0; i < GTM; i++) ra[i] = As[k][ty * GTM + i];
            #pragma unroll
            for (int j = 0; j < GTN; j++) rb[j] = Bs[k][tx * GTN + j];
            #pragma unroll
            for (int i = 0; i < GTM; i++)
                #pragma unroll
                for (int j = 0; j < GTN; j++)
                    acc[i][j] = fmaf(ra[i], rb[j], acc[i][j]);
        }
        __syncthreads();
    }

    #pragma unroll
    for (int i = 0; i < GTM; i++) {
        float* crow = C + (size_t)(brow + ty * GTM + i) * N + bcol + tx * GTN;
        #pragma unroll
        for (int j = 0; j < GTN; j += 4) {
            float4 v = make_float4(acc[i][j], acc[i][j+1], acc[i][j+2], acc[i][j+3]);
            *(float4*)(crow + j) = v;
        }
    }
}

// ============================ RoPE ===========================================
// Applies rotary to q (in g_q) and k (first half of g_kv), in place.
__global__ void rope_kernel(const float* __restrict__ rot,
                            float* __restrict__ q, float* __restrict__ kv) {
    int idx = blockIdx.x * blockDim.x + threadIdx.x;
    const int TOT = ROWS * HEADS * 32;
    if (idx >= TOT) return;
    int d = idx & 31;
    int h = (idx >> 5) & 31;
    int m = idx >> 10;
    int n = m & (SEQ - 1);

    float r0 = rot[n * DHEAD + d];
    float r1 = rot[n * DHEAD + d + 32];
    float c0 = cosf(r0), s0 = sinf(r0);
    float c1 = cosf(r1), s1 = sinf(r1);

    float* qp = q + (size_t)m * DIM_INNER + h * DHEAD;
    float q0 = qp[d], q1 = qp[d + 32];
    qp[d]      = q0 * c0 - q1 * s0;
    qp[d + 32] = q1 * c1 + q0 * s1;

    float* kp = kv + (size_t)m * (2 * DIM_INNER) + h * DHEAD;
    float k0 = kp[d], k1 = kp[d + 32];
    kp[d]      = k0 * c0 - k1 * s0;
    kp[d + 32] = k1 * c1 + k0 * s1;
}

// ============================ Flash attention ================================
// BM=BN=64, D=64, 256 threads: (ty,tx) 16x16 grid, each 4x4 microtile.
#define FBM 64
#define FBN 64
#define FLDS 65    // padded row stride (floats)
#define FSMEM (4 * FBM * FLDS * (int)sizeof(float))   // Qs,Ks,Vs,Ps

__global__ void __launch_bounds__(256)
flash_attn_kernel(const float* __restrict__ q, const float* __restrict__ kv,
                  float* __restrict__ ao) {
    extern __shared__ float sm[];
    float* Qs = sm;
    float* Ks = sm + FBM * FLDS;
    float* Vs = sm + 2 * FBM * FLDS;
    float* Ps = sm + 3 * FBM * FLDS;

    const int i0 = blockIdx.x * FBM;
    const int bh = blockIdx.y;
    const int b  = bh >> 5;      // /HEADS
    const int h  = bh & 31;

    const int tid = threadIdx.x;
    const int ty = tid >> 4, tx = tid & 15;

    const float scale = 0.125f;  // 1/sqrt(64)

    // ---- load Q tile (scaled) ----
    {
        int d4 = (tid & 15) * 4;
        int r0 = tid >> 4;
        #pragma unroll
        for (int it = 0; it < 4; it++) {
            int r = r0 + it * 16;
            float4 v = *(const float4*)&q[(size_t)(b * SEQ + i0 + r) * DIM_INNER + h * DHEAD + d4];
            Qs[r * FLDS + d4 + 0] = v.x * scale;
            Qs[r * FLDS + d4 + 1] = v.y * scale;
            Qs[r * FLDS + d4 + 2] = v.z * scale;
            Qs[r * FLDS + d4 + 3] = v.w * scale;
        }
    }

    float accO[4][4];
    #pragma unroll
    for (int i = 0; i < 4; i++)
        #pragma unroll
        for (int j = 0; j < 4; j++) accO[i][j] = 0.f;
    float mrow[4], lrow[4];
    #pragma unroll
    for (int i = 0; i < 4; i++) { mrow[i] = -1e30f; lrow[i] = 0.f; }

    for (int j0 = 0; j0 <= i0; j0 += FBN) {
        // ---- load K,V tiles ----
        {
            int d4 = (tid & 15) * 4;
            int r0 = tid >> 4;
            #pragma unroll
            for (int it = 0; it < 4; it++) {
                int r = r0 + it * 16;
                size_t base = (size_t)(b * SEQ + j0 + r) * (2 * DIM_INNER) + h * DHEAD;
                float4 kvk = *(const float4*)&kv[base + d4];
                Ks[r * FLDS + d4 + 0] = kvk.x;
                Ks[r * FLDS + d4 + 1] = kvk.y;
                Ks[r * FLDS + d4 + 2] = kvk.z;
                Ks[r * FLDS + d4 + 3] = kvk.w;
                float4 kvv = *(const float4*)&kv[base + DIM_INNER + d4];
                Vs[r * FLDS + d4 + 0] = kvv.x;
                Vs[r * FLDS + d4 + 1] = kvv.y;
                Vs[r * FLDS + d4 + 2] = kvv.z;
                Vs[r * FLDS + d4 + 3] = kvv.w;
            }
        }
        __syncthreads();

        // ---- S = Q @ K^T (4x4 per thread) ----
        float s[4][4];
        #pragma unroll
        for (int i = 0; i < 4; i++)
            #pragma unroll
            for (int j = 0; j < 4; j++) s[i][j] = 0.f;

        #pragma unroll 8
        for (int d = 0; d < DHEAD; d++) {
            float rq[4], rk[4];
            #pragma unroll
            for (int i = 0; i < 4; i++) rq[i] = Qs[(ty * 4 + i) * FLDS + d];
            #pragma unroll
            for (int j = 0; j < 4; j++) rk[j] = Ks[(tx * 4 + j) * FLDS + d];
            #pragma unroll
            for (int i = 0; i < 4; i++)
                #pragma unroll
                for (int j = 0; j < 4; j++)
                    s[i][j] = fmaf(rq[i], rk[j], s[i][j]);
        }

        // ---- causal mask on diagonal block ----
        if (j0 == i0) {
            #pragma unroll
            for (int i = 0; i < 4; i++) {
                int gi = ty * 4 + i;
                #pragma unroll
                for (int j = 0; j < 4; j++) {
                    int gj = tx * 4 + j;
                    if (gj > gi) s[i][j] = -1e30f;
                }
            }
        }

        // ---- online softmax update ----
        float scaleO[4];
        #pragma unroll
        for (int i = 0; i < 4; i++) {
            float rm = fmaxf(fmaxf(s[i][0], s[i][1]), fmaxf(s[i][2], s[i][3]));
            #pragma unroll
            for (int off = 8; off > 0; off >>= 1)
                rm = fmaxf(rm, __shfl_xor_sync(0xffffffffu, rm, off));
            float mnew = fmaxf(mrow[i], rm);
            float so = __expf(mrow[i] - mnew);
            float rs = 0.f;
            #pragma unroll
            for (int j = 0; j < 4; j++) {
                s[i][j] = __expf(s[i][j] - mnew);
                rs += s[i][j];
            }
            #pragma unroll
            for (int off = 8; off > 0; off >>= 1)
                rs += __shfl_xor_sync(0xffffffffu, rs, off);
            lrow[i] = lrow[i] * so + rs;
            mrow[i] = mnew;
            scaleO[i] = so;
        }

        // rescale O
        #pragma unroll
        for (int i = 0; i < 4; i++)
            #pragma unroll
            for (int j = 0; j < 4; j++) accO[i][j] *= scaleO[i];

        // ---- write P to shared ----
        #pragma unroll
        for (int i = 0; i < 4; i++)
            #pragma unroll
            for (int j = 0; j < 4; j++)
                Ps[(ty * 4 + i) * FLDS + tx * 4 + j] = s[i][j];
        __syncthreads();

        // ---- O += P @ V ----
        #pragma unroll 8
        for (int j = 0; j < FBN; j++) {
            float rp[4], rv[4];
            #pragma unroll
            for (int i = 0; i < 4; i++) rp[i] = Ps[(ty * 4 + i) * FLDS + j];
            #pragma unroll
            for (int c = 0; c < 4; c++) rv[c] = Vs[j * FLDS + tx * 4 + c];
            #pragma unroll
            for (int i = 0; i < 4; i++)
                #pragma unroll
                for (int c = 0; c < 4; c++)
                    accO[i][c] = fmaf(rp[i], rv[c], accO[i][c]);
        }
        __syncthreads();   // before K/V/P overwritten next iteration
    }

    // ---- epilogue: normalize & store ----
    #pragma unroll
    for (int i = 0; i < 4; i++) {
        int r = i0 + ty * 4 + i;
        float inv = 1.f / lrow[i];
        float* op = ao + (size_t)(b * SEQ + r) * DIM_INNER + h * DHEAD + tx * 4;
        #pragma unroll
        for (int c = 0; c < 4; c++) op[c] = accO[i][c] * inv;
    }
}

// ============================ Launch =========================================
extern "C" void kernel_launch(void* const* d_in, const int* in_sizes, int n_in,
                              void* d_out, int out_size) {
    const float* x     = (const float*)d_in[0];
    const float* rot   = (const float*)d_in[1];
    const float* gamma = (const float*)d_in[2];
    const float* Wq    = (const float*)d_in[3];
    const float* Wkv   = (const float*)d_in[4];
    const float* Wout  = (const float*)d_in[5];
    float* out = (float*)d_out;

    float *xn, *q, *kv, *ao;
    cudaGetSymbolAddress((void**)&xn, g_xn);
    cudaGetSymbolAddress((void**)&q,  g_q);
    cudaGetSymbolAddress((void**)&kv, g_kv);
    cudaGetSymbolAddress((void**)&ao, g_ao);

    // 1) RMSNorm
    rmsnorm_kernel<<<ROWS, 256>>>(x, gamma, xn);

    // 2) Q = xn @ Wq   [4096,2048]x[2048,2048]
    sgemm_kernel<<<dim3(DIM_INNER / GBN, ROWS / GBM), 256>>>(xn, Wq, q, ROWS, DIM_INNER, DIM);
    //    KV = xn @ Wkv [4096,2048]x[2048,4096]
    sgemm_kernel<<<dim3(2 * DIM_INNER / GBN, ROWS / GBM), 256>>>(xn, Wkv, kv, ROWS, 2 * DIM_INNER, DIM);

    // 3) RoPE on q and k
    {
        int tot = ROWS * HEADS * 32;
        rope_kernel<<<(tot + 255) / 256, 256>>>(rot, q, kv);
    }

    // 4) causal flash attention
    cudaFuncSetAttribute(flash_attn_kernel,
                         cudaFuncAttributeMaxDynamicSharedMemorySize, FSMEM);
    flash_attn_kernel<<<dim3(SEQ / FBM, BATCH * HEADS), 256, FSMEM>>>(q, kv, ao);

    // 5) out = ao @ Wout [4096,2048]x[2048,2048]
    sgemm_kernel<<<dim3(DIM / GBN, ROWS / GBM), 256>>>(ao, Wout, out, ROWS, DIM, DIM);
}

// round 2
// speedup vs baseline: 1.8752x; 1.8752x over previous
#include <cuda_runtime.h>
#include <math.h>
#include <stdint.h>

// Problem constants
#define BATCH 2
#define SEQ   2048
#define DIM   2048
#define HEADS 32
#define DHEAD 64
#define ROWS  (BATCH * SEQ)          // 4096
#define DIM_INNER (HEADS * DHEAD)    // 2048

// ---------------- Scratch (static device globals — allocation-free) ----------
__device__ float g_xn[ROWS * DIM];          // 32 MB  rmsnorm(x)
__device__ float g_q [ROWS * DIM_INNER];    // 32 MB  q  [m, h*64+d]
__device__ float g_kv[ROWS * 2 * DIM_INNER];// 64 MB  k | v
__device__ float g_ao[ROWS * DIM_INNER];    // 32 MB  attention output

// ============================ RMSNorm ========================================
__global__ void rmsnorm_kernel(const float* __restrict__ x,
                               const float* __restrict__ gamma,
                               float* __restrict__ xn) {
    int row = blockIdx.x;
    const float* xr = x + (size_t)row * DIM;
    float ss = 0.f;
    for (int i = threadIdx.x; i < DIM; i += blockDim.x) {
        float v = xr[i];
        ss += v * v;
    }
    __shared__ float red[32];
    int lane = threadIdx.x & 31, wid = threadIdx.x >> 5;
    #pragma unroll
    for (int off = 16; off > 0; off >>= 1) ss += __shfl_xor_sync(0xffffffffu, ss, off);
    if (lane == 0) red[wid] = ss;
    __syncthreads();
    if (wid == 0) {
        float v = (lane < (blockDim.x >> 5)) ? red[lane] : 0.f;
        #pragma unroll
        for (int off = 16; off > 0; off >>= 1) v += __shfl_xor_sync(0xffffffffu, v, off);
        if (lane == 0) red[0] = v;
    }
    __syncthreads();
    float norm = sqrtf(red[0]);
    float s = sqrtf((float)DIM) / fmaxf(norm, 1e-12f);
    float* xo = xn + (size_t)row * DIM;
    for (int i = threadIdx.x; i < DIM; i += blockDim.x)
        xo[i] = xr[i] * s * gamma[i];
}

// ======================= TF32 tensor-core GEMM ===============================
// C[M,N] = A[M,K] @ B[K,N], row-major, M%128==0, N%128==0, K%32==0.
// Block 128x128x32; 256 threads = 8 warps (2 M x 4 N); warp tile 64x32;
// mma.sync.aligned.m16n8k8.tf32 with fp32 accumulate.

__device__ __forceinline__ float f2tf32(float x) {
    uint32_t u;
    asm("cvt.rna.tf32.f32 %0, %1;" : "=r"(u) : "f"(x));
    return __uint_as_float(u);
}

__device__ __forceinline__ void mma_tf32(float d[4],
                                         uint32_t a0, uint32_t a1, uint32_t a2, uint32_t a3,
                                         uint32_t b0, uint32_t b1) {
    asm volatile(
        "mma.sync.aligned.m16n8k8.row.col.f32.tf32.tf32.f32 "
        "{%0,%1,%2,%3}, {%4,%5,%6,%7}, {%8,%9}, {%0,%1,%2,%3};"
        : "+f"(d[0]), "+f"(d[1]), "+f"(d[2]), "+f"(d[3])
        : "r"(a0), "r"(a1), "r"(a2), "r"(a3), "r"(b0), "r"(b1));
}

#define TBM 128
#define TBN 128
#define TBK 32
#define ASTRIDE 36    // 32 + 4 pad
#define BSTRIDE 132   // 128 + 4 pad

__global__ void __launch_bounds__(256)
tf32_gemm(const float* __restrict__ A, const float* __restrict__ B,
          float* __restrict__ C, int M, int N, int K) {
    __shared__ float As[TBM][ASTRIDE];   // [m][k]
    __shared__ float Bs[TBK][BSTRIDE];   // [k][n]

    const int tid  = threadIdx.x;
    const int wid  = tid >> 5;
    const int lane = tid & 31;
    const int wm = (wid >> 2) * 64;   // warp M offset (0 or 64)
    const int wn = (wid & 3) * 32;    // warp N offset (0..96)
    const int brow = blockIdx.y * TBM;
    const int bcol = blockIdx.x * TBN;

    // global loaders: A -> rows ar+{0,32,64,96}, cols [ac, ac+4)
    const int ar = tid >> 3;          // 0..31
    const int ac = (tid & 7) * 4;     // 0..28
    const float* Ap = A + (size_t)(brow + ar) * K + ac;
    // B -> row bkr, cols bc+{0,32,64,96}
    const int bkr = tid >> 3;         // 0..31
    const int bc  = (tid & 7) * 4;    // 0..28
    const float* Bp = B + (size_t)bkr * N + bcol + bc;

    float4 abuf[4], bbuf[4];
    #pragma unroll
    for (int i = 0; i < 4; i++) abuf[i] = *(const float4*)(Ap + (size_t)(i * 32) * K);
    #pragma unroll
    for (int i = 0; i < 4; i++) bbuf[i] = *(const float4*)(Bp + i * 32);

    float acc[16][4];
    #pragma unroll
    for (int i = 0; i < 16; i++)
        #pragma unroll
        for (int j = 0; j < 4; j++) acc[i][j] = 0.f;

    const int KT = K / TBK;
    for (int kt = 0; kt < KT; kt++) {
        // store current tile into shared (with RNA rounding to tf32)
        #pragma unroll
        for (int i = 0; i < 4; i++) {
            float4 v = abuf[i];
            v.x = f2tf32(v.x); v.y = f2tf32(v.y); v.z = f2tf32(v.z); v.w = f2tf32(v.w);
            *(float4*)&As[ar + i * 32][ac] = v;
        }
        #pragma unroll
        for (int i = 0; i < 4; i++) {
            float4 v = bbuf[i];
            v.x = f2tf32(v.x); v.y = f2tf32(v.y); v.z = f2tf32(v.z); v.w = f2tf32(v.w);
            *(float4*)&Bs[bkr][bc + i * 32] = v;
        }
        __syncthreads();

        // prefetch next tile
        if (kt + 1 < KT) {
            const float* Ap2 = Ap + (kt + 1) * TBK;
            #pragma unroll
            for (int i = 0; i < 4; i++) abuf[i] = *(const float4*)(Ap2 + (size_t)(i * 32) * K);
            const float* Bp2 = Bp + (size_t)(kt + 1) * TBK * N;
            #pragma unroll
            for (int i = 0; i < 4; i++) bbuf[i] = *(const float4*)(Bp2 + i * 32);
        }

        // compute: 4 k8 steps
        #pragma unroll
        for (int kk = 0; kk < TBK; kk += 8) {
            uint32_t afrag[4][4];
            #pragma unroll
            for (int mf = 0; mf < 4; mf++) {
                int r = wm + mf * 16 + (lane >> 2);
                int c = kk + (lane & 3);
                afrag[mf][0] = __float_as_uint(As[r][c]);
                afrag[mf][1] = __float_as_uint(As[r + 8][c]);
                afrag[mf][2] = __float_as_uint(As[r][c + 4]);
                afrag[mf][3] = __float_as_uint(As[r + 8][c + 4]);
            }
            #pragma unroll
            for (int nf = 0; nf < 4; nf++) {
                int col = wn + nf * 8 + (lane >> 2);
                int kr  = kk + (lane & 3);
                uint32_t b0 = __float_as_uint(Bs[kr][col]);
                uint32_t b1 = __float_as_uint(Bs[kr + 4][col]);
                #pragma unroll
                for (int mf = 0; mf < 4; mf++)
                    mma_tf32(acc[mf * 4 + nf], afrag[mf][0], afrag[mf][1],
                             afrag[mf][2], afrag[mf][3], b0, b1);
            }
        }
        __syncthreads();
    }

    // epilogue
    #pragma unroll
    for (int mf = 0; mf < 4; mf++) {
        int row = brow + wm + mf * 16 + (lane >> 2);
        #pragma unroll
        for (int nf = 0; nf < 4; nf++) {
            int col = bcol + wn + nf * 8 + (lane & 3) * 2;
            float* c0 = C + (size_t)row * N + col;
            float* c1 = C + (size_t)(row + 8) * N + col;
            *(float2*)c0 = make_float2(acc[mf * 4 + nf][0], acc[mf * 4 + nf][1]);
            *(float2*)c1 = make_float2(acc[mf * 4 + nf][2], acc[mf * 4 + nf][3]);
        }
    }
}

// ============================ RoPE ===========================================
__global__ void rope_kernel(const float* __restrict__ rot,
                            float* __restrict__ q, float* __restrict__ kv) {
    int idx = blockIdx.x * blockDim.x + threadIdx.x;
    const int TOT = ROWS * HEADS * 32;
    if (idx >= TOT) return;
    int d = idx & 31;
    int h = (idx >> 5) & 31;
    int m = idx >> 10;
    int n = m & (SEQ - 1);

    float r0 = rot[n * DHEAD + d];
    float r1 = rot[n * DHEAD + d + 32];
    float c0 = cosf(r0), s0 = sinf(r0);
    float c1 = cosf(r1), s1 = sinf(r1);

    float* qp = q + (size_t)m * DIM_INNER + h * DHEAD;
    float q0 = qp[d], q1 = qp[d + 32];
    qp[d]      = q0 * c0 - q1 * s0;
    qp[d + 32] = q1 * c1 + q0 * s1;

    float* kp = kv + (size_t)m * (2 * DIM_INNER) + h * DHEAD;
    float k0 = kp[d], k1 = kp[d + 32];
    kp[d]      = k0 * c0 - k1 * s0;
    kp[d + 32] = k1 * c1 + k0 * s1;
}

// ============================ Flash attention ================================
// BM=BN=64, D=64, 256 threads: (ty,tx) 16x16 grid, each 4x4 microtile.
#define FBM 64
#define FBN 64
#define FLDS 65    // padded row stride (floats)
#define FSMEM (4 * FBM * FLDS * (int)sizeof(float))   // Qs,Ks,Vs,Ps

__global__ void __launch_bounds__(256)
flash_attn_kernel(const float* __restrict__ q, const float* __restrict__ kv,
                  float* __restrict__ ao) {
    extern __shared__ float sm[];
    float* Qs = sm;
    float* Ks = sm + FBM * FLDS;
    float* Vs = sm + 2 * FBM * FLDS;
    float* Ps = sm + 3 * FBM * FLDS;

    const int i0 = blockIdx.x * FBM;
    const int bh = blockIdx.y;
    const int b  = bh >> 5;      // /HEADS
    const int h  = bh & 31;

    const int tid = threadIdx.x;
    const int ty = tid >> 4, tx = tid & 15;

    const float scale = 0.125f;  // 1/sqrt(64)

    // ---- load Q tile (scaled) ----
    {
        int d4 = (tid & 15) * 4;
        int r0 = tid >> 4;
        #pragma unroll
        for (int it = 0; it < 4; it++) {
            int r = r0 + it * 16;
            float4 v = *(const float4*)&q[(size_t)(b * SEQ + i0 + r) * DIM_INNER + h * DHEAD + d4];
            Qs[r * FLDS + d4 + 0] = v.x * scale;
            Qs[r * FLDS + d4 + 1] = v.y * scale;
            Qs[r * FLDS + d4 + 2] = v.z * scale;
            Qs[r * FLDS + d4 + 3] = v.w * scale;
        }
    }

    float accO[4][4];
    #pragma unroll
    for (int i = 0; i < 4; i++)
        #pragma unroll
        for (int j = 0; j < 4; j++) accO[i][j] = 0.f;
    float mrow[4], lrow[4];
    #pragma unroll
    for (int i = 0; i < 4; i++) { mrow[i] = -1e30f; lrow[i] = 0.f; }

    for (int j0 = 0; j0 <= i0; j0 += FBN) {
        // ---- load K,V tiles ----
        {
            int d4 = (tid & 15) * 4;
            int r0 = tid >> 4;
            #pragma unroll
            for (int it = 0; it < 4; it++) {
                int r = r0 + it * 16;
                size_t base = (size_t)(b * SEQ + j0 + r) * (2 * DIM_INNER) + h * DHEAD;
                float4 kvk = *(const float4*)&kv[base + d4];
                Ks[r * FLDS + d4 + 0] = kvk.x;
                Ks[r * FLDS + d4 + 1] = kvk.y;
                Ks[r * FLDS + d4 + 2] = kvk.z;
                Ks[r * FLDS + d4 + 3] = kvk.w;
                float4 kvv = *(const float4*)&kv[base + DIM_INNER + d4];
                Vs[r * FLDS + d4 + 0] = kvv.x;
                Vs[r * FLDS + d4 + 1] = kvv.y;
                Vs[r * FLDS + d4 + 2] = kvv.z;
                Vs[r * FLDS + d4 + 3] = kvv.w;
            }
        }
        __syncthreads();

        // ---- S = Q @ K^T (4x4 per thread) ----
        float s[4][4];
        #pragma unroll
        for (int i = 0; i < 4; i++)
            #pragma unroll
            for (int j = 0; j < 4; j++) s[i][j] = 0.f;

        #pragma unroll 8
        for (int d = 0; d < DHEAD; d++) {
            float rq[4], rk[4];
            #pragma unroll
            for (int i = 0; i < 4; i++) rq[i] = Qs[(ty * 4 + i) * FLDS + d];
            #pragma unroll
            for (int j = 0; j < 4; j++) rk[j] = Ks[(tx * 4 + j) * FLDS + d];
            #pragma unroll
            for (int i = 0; i < 4; i++)
                #pragma unroll
                for (int j = 0; j < 4; j++)
                    s[i][j] = fmaf(rq[i], rk[j], s[i][j]);
        }

        // ---- causal mask on diagonal block ----
        if (j0 == i0) {
            #pragma unroll
            for (int i = 0; i < 4; i++) {
                int gi = ty * 4 + i;
                #pragma unroll
                for (int j = 0; j < 4; j++) {
                    int gj = tx * 4 + j;
                    if (gj > gi) s[i][j] = -1e30f;
                }
            }
        }

        // ---- online softmax update ----
        float scaleO[4];
        #pragma unroll
        for (int i = 0; i < 4; i++) {
            float rm = fmaxf(fmaxf(s[i][0], s[i][1]), fmaxf(s[i][2], s[i][3]));
            #pragma unroll
            for (int off = 8; off > 0; off >>= 1)
                rm = fmaxf(rm, __shfl_xor_sync(0xffffffffu, rm, off));
            float mnew = fmaxf(mrow[i], rm);
            float so = __expf(mrow[i] - mnew);
            float rs = 0.f;
            #pragma unroll
            for (int j = 0; j < 4; j++) {
                s[i][j] = __expf(s[i][j] - mnew);
                rs += s[i][j];
            }
            #pragma unroll
            for (int off = 8; off > 0; off >>= 1)
                rs += __shfl_xor_sync(0xffffffffu, rs, off);
            lrow[i] = lrow[i] * so + rs;
            mrow[i] = mnew;
            scaleO[i] = so;
        }

        // rescale O
        #pragma unroll
        for (int i = 0; i < 4; i++)
            #pragma unroll
            for (int j = 0; j < 4; j++) accO[i][j] *= scaleO[i];

        // ---- write P to shared ----
        #pragma unroll
        for (int i = 0; i < 4; i++)
            #pragma unroll
            for (int j = 0; j < 4; j++)
                Ps[(ty * 4 + i) * FLDS + tx * 4 + j] = s[i][j];
        __syncthreads();

        // ---- O += P @ V ----
        #pragma unroll 8
        for (int j = 0; j < FBN; j++) {
            float rp[4], rv[4];
            #pragma unroll
            for (int i = 0; i < 4; i++) rp[i] = Ps[(ty * 4 + i) * FLDS + j];
            #pragma unroll
            for (int c = 0; c < 4; c++) rv[c] = Vs[j * FLDS + tx * 4 + c];
            #pragma unroll
            for (int i = 0; i < 4; i++)
                #pragma unroll
                for (int c = 0; c < 4; c++)
                    accO[i][c] = fmaf(rp[i], rv[c], accO[i][c]);
        }
        __syncthreads();   // before K/V/P overwritten next iteration
    }

    // ---- epilogue: normalize & store ----
    #pragma unroll
    for (int i = 0; i < 4; i++) {
        int r = i0 + ty * 4 + i;
        float inv = 1.f / lrow[i];
        float* op = ao + (size_t)(b * SEQ + r) * DIM_INNER + h * DHEAD + tx * 4;
        #pragma unroll
        for (int c = 0; c < 4; c++) op[c] = accO[i][c] * inv;
    }
}

// ============================ Launch =========================================
extern "C" void kernel_launch(void* const* d_in, const int* in_sizes, int n_in,
                              void* d_out, int out_size) {
    const float* x     = (const float*)d_in[0];
    const float* rot   = (const float*)d_in[1];
    const float* gamma = (const float*)d_in[2];
    const float* Wq    = (const float*)d_in[3];
    const float* Wkv   = (const float*)d_in[4];
    const float* Wout  = (const float*)d_in[5];
    float* out = (float*)d_out;

    float *xn, *q, *kv, *ao;
    cudaGetSymbolAddress((void**)&xn, g_xn);
    cudaGetSymbolAddress((void**)&q,  g_q);
    cudaGetSymbolAddress((void**)&kv, g_kv);
    cudaGetSymbolAddress((void**)&ao, g_ao);

    // 1) RMSNorm
    rmsnorm_kernel<<<ROWS, 256>>>(x, gamma, xn);

    // 2) TF32 tensor-core projections
    tf32_gemm<<<dim3(DIM_INNER / TBN, ROWS / TBM), 256>>>(xn, Wq, q, ROWS, DIM_INNER, DIM);
    tf32_gemm<<<dim3(2 * DIM_INNER / TBN, ROWS / TBM), 256>>>(xn, Wkv, kv, ROWS, 2 * DIM_INNER, DIM);

    // 3) RoPE on q and k
    {
        int tot = ROWS * HEADS * 32;
        rope_kernel<<<(tot + 255) / 256, 256>>>(rot, q, kv);
    }

    // 4) causal flash attention
    cudaFuncSetAttribute(flash_attn_kernel,
                         cudaFuncAttributeMaxDynamicSharedMemorySize, FSMEM);
    flash_attn_kernel<<<dim3(SEQ / FBM, BATCH * HEADS), 256, FSMEM>>>(q, kv, ao);

    // 5) out projection
    tf32_gemm<<<dim3(DIM / TBN, ROWS / TBM), 256>>>(ao, Wout, out, ROWS, DIM, DIM);
}

// round 4
// speedup vs baseline: 2.9193x; 1.5568x over previous
#include <cuda_runtime.h>
#include <math.h>
#include <stdint.h>

// Problem constants
#define BATCH 2
#define SEQ   2048
#define DIM   2048
#define HEADS 32
#define DHEAD 64
#define ROWS  (BATCH * SEQ)          // 4096
#define DIM_INNER (HEADS * DHEAD)    // 2048

// ---------------- Scratch (static device globals — allocation-free) ----------
__device__ float g_xn[ROWS * DIM];
__device__ float g_q [ROWS * DIM_INNER];
__device__ float g_kv[ROWS * 2 * DIM_INNER];
__device__ float g_ao[ROWS * DIM_INNER];

// ============================ helpers ========================================
__device__ __forceinline__ float f2tf32(float x) {
    uint32_t u;
    asm("cvt.rna.tf32.f32 %0, %1;" : "=r"(u) : "f"(x));
    return __uint_as_float(u);
}
__device__ __forceinline__ uint32_t f2tf32u(float x) {
    uint32_t u;
    asm("cvt.rna.tf32.f32 %0, %1;" : "=r"(u) : "f"(x));
    return u;
}
__device__ __forceinline__ void mma_tf32(float d[4],
                                         uint32_t a0, uint32_t a1, uint32_t a2, uint32_t a3,
                                         uint32_t b0, uint32_t b1) {
    asm volatile(
        "mma.sync.aligned.m16n8k8.row.col.f32.tf32.tf32.f32 "
        "{%0,%1,%2,%3}, {%4,%5,%6,%7}, {%8,%9}, {%0,%1,%2,%3};"
        : "+f"(d[0]), "+f"(d[1]), "+f"(d[2]), "+f"(d[3])
        : "r"(a0), "r"(a1), "r"(a2), "r"(a3), "r"(b0), "r"(b1));
}

// ============================ RMSNorm ========================================
__global__ void rmsnorm_kernel(const float* __restrict__ x,
                               const float* __restrict__ gamma,
                               float* __restrict__ xn) {
    int row = blockIdx.x;
    const float* xr = x + (size_t)row * DIM;
    float ss = 0.f;
    for (int i = threadIdx.x; i < DIM; i += blockDim.x) {
        float v = xr[i];
        ss += v * v;
    }
    __shared__ float red[32];
    int lane = threadIdx.x & 31, wid = threadIdx.x >> 5;
    #pragma unroll
    for (int off = 16; off > 0; off >>= 1) ss += __shfl_xor_sync(0xffffffffu, ss, off);
    if (lane == 0) red[wid] = ss;
    __syncthreads();
    if (wid == 0) {
        float v = (lane < (blockDim.x >> 5)) ? red[lane] : 0.f;
        #pragma unroll
        for (int off = 16; off > 0; off >>= 1) v += __shfl_xor_sync(0xffffffffu, v, off);
        if (lane == 0) red[0] = v;
    }
    __syncthreads();
    float norm = sqrtf(red[0]);
    float s = sqrtf((float)DIM) / fmaxf(norm, 1e-12f);
    float* xo = xn + (size_t)row * DIM;
    for (int i = threadIdx.x; i < DIM; i += blockDim.x)
        xo[i] = xr[i] * s * gamma[i];
}

// ======================= TF32 tensor-core GEMM ===============================
#define TBM 128
#define TBN 128
#define TBK 32
#define ASTRIDE 36
#define BSTRIDE 132

__global__ void __launch_bounds__(256)
tf32_gemm(const float* __restrict__ A, const float* __restrict__ B,
          float* __restrict__ C, int M, int N, int K) {
    __shared__ float As[TBM][ASTRIDE];
    __shared__ float Bs[TBK][BSTRIDE];

    const int tid  = threadIdx.x;
    const int wid  = tid >> 5;
    const int lane = tid & 31;
    const int wm = (wid >> 2) * 64;
    const int wn = (wid & 3) * 32;
    const int brow = blockIdx.y * TBM;
    const int bcol = blockIdx.x * TBN;

    const int ar = tid >> 3;
    const int ac = (tid & 7) * 4;
    const float* Ap = A + (size_t)(brow + ar) * K + ac;
    const int bkr = tid >> 3;
    const int bc  = (tid & 7) * 4;
    const float* Bp = B + (size_t)bkr * N + bcol + bc;

    float4 abuf[4], bbuf[4];
    #pragma unroll
    for (int i = 0; i < 4; i++) abuf[i] = *(const float4*)(Ap + (size_t)(i * 32) * K);
    #pragma unroll
    for (int i = 0; i < 4; i++) bbuf[i] = *(const float4*)(Bp + i * 32);

    float acc[16][4];
    #pragma unroll
    for (int i = 0; i < 16; i++)
        #pragma unroll
        for (int j = 0; j < 4; j++) acc[i][j] = 0.f;

    const int KT = K / TBK;
    for (int kt = 0; kt < KT; kt++) {
        #pragma unroll
        for (int i = 0; i < 4; i++) {
            float4 v = abuf[i];
            v.x = f2tf32(v.x); v.y = f2tf32(v.y); v.z = f2tf32(v.z); v.w = f2tf32(v.w);
            *(float4*)&As[ar + i * 32][ac] = v;
        }
        #pragma unroll
        for (int i = 0; i < 4; i++) {
            float4 v = bbuf[i];
            v.x = f2tf32(v.x); v.y = f2tf32(v.y); v.z = f2tf32(v.z); v.w = f2tf32(v.w);
            *(float4*)&Bs[bkr][bc + i * 32] = v;
        }
        __syncthreads();

        if (kt + 1 < KT) {
            const float* Ap2 = Ap + (kt + 1) * TBK;
            #pragma unroll
            for (int i = 0; i < 4; i++) abuf[i] = *(const float4*)(Ap2 + (size_t)(i * 32) * K);
            const float* Bp2 = Bp + (size_t)(kt + 1) * TBK * N;
            #pragma unroll
            for (int i = 0; i < 4; i++) bbuf[i] = *(const float4*)(Bp2 + i * 32);
        }

        #pragma unroll
        for (int kk = 0; kk < TBK; kk += 8) {
            uint32_t afrag[4][4];
            #pragma unroll
            for (int mf = 0; mf < 4; mf++) {
                int r = wm + mf * 16 + (lane >> 2);
                int c = kk + (lane & 3);
                afrag[mf][0] = __float_as_uint(As[r][c]);
                afrag[mf][1] = __float_as_uint(As[r + 8][c]);
                afrag[mf][2] = __float_as_uint(As[r][c + 4]);
                afrag[mf][3] = __float_as_uint(As[r + 8][c + 4]);
            }
            #pragma unroll
            for (int nf = 0; nf < 4; nf++) {
                int col = wn + nf * 8 + (lane >> 2);
                int kr  = kk + (lane & 3);
                uint32_t b0 = __float_as_uint(Bs[kr][col]);
                uint32_t b1 = __float_as_uint(Bs[kr + 4][col]);
                #pragma unroll
                for (int mf = 0; mf < 4; mf++)
                    mma_tf32(acc[mf * 4 + nf], afrag[mf][0], afrag[mf][1],
                             afrag[mf][2], afrag[mf][3], b0, b1);
            }
        }
        __syncthreads();
    }

    #pragma unroll
    for (int mf = 0; mf < 4; mf++) {
        int row = brow + wm + mf * 16 + (lane >> 2);
        #pragma unroll
        for (int nf = 0; nf < 4; nf++) {
            int col = bcol + wn + nf * 8 + (lane & 3) * 2;
            float* c0 = C + (size_t)row * N + col;
            float* c1 = C + (size_t)(row + 8) * N + col;
            *(float2*)c0 = make_float2(acc[mf * 4 + nf][0], acc[mf * 4 + nf][1]);
            *(float2*)c1 = make_float2(acc[mf * 4 + nf][2], acc[mf * 4 + nf][3]);
        }
    }
}

// ============================ RoPE ===========================================
__global__ void rope_kernel(const float* __restrict__ rot,
                            float* __restrict__ q, float* __restrict__ kv) {
    int idx = blockIdx.x * blockDim.x + threadIdx.x;
    const int TOT = ROWS * HEADS * 32;
    if (idx >= TOT) return;
    int d = idx & 31;
    int h = (idx >> 5) & 31;
    int m = idx >> 10;
    int n = m & (SEQ - 1);

    float r0 = rot[n * DHEAD + d];
    float r1 = rot[n * DHEAD + d + 32];
    float c0 = cosf(r0), s0 = sinf(r0);
    float c1 = cosf(r1), s1 = sinf(r1);

    float* qp = q + (size_t)m * DIM_INNER + h * DHEAD;
    float q0 = qp[d], q1 = qp[d + 32];
    qp[d]      = q0 * c0 - q1 * s0;
    qp[d + 32] = q1 * c1 + q0 * s1;

    float* kp = kv + (size_t)m * (2 * DIM_INNER) + h * DHEAD;
    float k0 = kp[d], k1 = kp[d + 32];
    kp[d]      = k0 * c0 - k1 * s0;
    kp[d + 32] = k1 * c1 + k0 * s1;
}

// ==================== Flash attention (tf32 tensor cores) ====================
// BM=BN=64, 4 warps; warp w owns rows [w*16, w*16+16) of the i-tile.
// mma m16n8k8 tf32; online softmax in fp32 registers.
#define AKS 68   // Ks row stride (floats)
#define AVS 72   // Vs row stride
#define APS 68   // Ps row stride
#define FSMEM2 ((64 * AKS + 64 * AVS + 64 * APS) * (int)sizeof(float))

__global__ void __launch_bounds__(128)
flash_mma_kernel(const float* __restrict__ q, const float* __restrict__ kv,
                 float* __restrict__ ao) {
    extern __shared__ float sm[];
    float* Ks = sm;
    float* Vs = sm + 64 * AKS;
    float* Ps = Vs + 64 * AVS;

    const int bh = blockIdx.y;
    const int b  = bh >> 5;
    const int h  = bh & 31;
    const int i0 = (gridDim.x - 1 - blockIdx.x) * 64;  // heavy tiles first

    const int tid  = threadIdx.x;
    const int wid  = tid >> 5;
    const int lane = tid & 31;
    const int qr   = lane >> 2;   // 0..7
    const int qc   = lane & 3;    // 0..3

    // ---- load Q tile into A-fragments (scaled by 1/8, tf32-rounded) ----
    uint32_t qf[8][4];
    {
        const float* qb = q + (size_t)(b * SEQ + i0 + wid * 16) * DIM_INNER + h * DHEAD;
        #pragma unroll
        for (int kk = 0; kk < 8; kk++) {
            qf[kk][0] = f2tf32u(qb[(size_t)qr * DIM_INNER + kk * 8 + qc] * 0.125f);
            qf[kk][1] = f2tf32u(qb[(size_t)(qr + 8) * DIM_INNER + kk * 8 + qc] * 0.125f);
            qf[kk][2] = f2tf32u(qb[(size_t)qr * DIM_INNER + kk * 8 + 4 + qc] * 0.125f);
            qf[kk][3] = f2tf32u(qb[(size_t)(qr + 8) * DIM_INNER + kk * 8 + 4 + qc] * 0.125f);
        }
    }

    float oacc[8][4];
    #pragma unroll
    for (int i = 0; i < 8; i++)
        #pragma unroll
        for (int j = 0; j < 4; j++) oacc[i][j] = 0.f;
    float m_lo = -1e30f, m_hi = -1e30f, l_lo = 0.f, l_hi = 0.f;

    for (int j0 = 0; j0 <= i0; j0 += 64) {
        // ---- stage K,V tiles (tf32-rounded) ----
        {
            const float* kvb = kv + (size_t)(b * SEQ + j0) * (2 * DIM_INNER) + h * DHEAD;
            #pragma unroll
            for (int it = 0; it < 8; it++) {
                int idx = tid + it * 128;
                int row = idx >> 4;
                int c4  = (idx & 15) * 4;
                float4 vk = *(const float4*)(kvb + (size_t)row * (2 * DIM_INNER) + c4);
                Ks[row * AKS + c4 + 0] = f2tf32(vk.x);
                Ks[row * AKS + c4 + 1] = f2tf32(vk.y);
                Ks[row * AKS + c4 + 2] = f2tf32(vk.z);
                Ks[row * AKS + c4 + 3] = f2tf32(vk.w);
                float4 vv = *(const float4*)(kvb + (size_t)row * (2 * DIM_INNER) + DIM_INNER + c4);
                Vs[row * AVS + c4 + 0] = f2tf32(vv.x);
                Vs[row * AVS + c4 + 1] = f2tf32(vv.y);
                Vs[row * AVS + c4 + 2] = f2tf32(vv.z);
                Vs[row * AVS + c4 + 3] = f2tf32(vv.w);
            }
        }
        __syncthreads();

        // ---- S = Q @ K^T ----
        float sacc[8][4];
        #pragma unroll
        for (int i = 0; i < 8; i++)
            #pragma unroll
            for (int j = 0; j < 4; j++) sacc[i][j] = 0.f;

        #pragma unroll
        for (int kk = 0; kk < 8; kk++) {
            #pragma unroll
            for (int nf = 0; nf < 8; nf++) {
                int col = nf * 8 + qr;
                uint32_t b0 = __float_as_uint(Ks[col * AKS + kk * 8 + qc]);
                uint32_t b1 = __float_as_uint(Ks[col * AKS + kk * 8 + 4 + qc]);
                mma_tf32(sacc[nf], qf[kk][0], qf[kk][1], qf[kk][2], qf[kk][3], b0, b1);
            }
        }

        // ---- causal mask (diagonal block only) ----
        if (j0 == i0) {
            int gi_lo = wid * 16 + qr;
            int gi_hi = gi_lo + 8;
            #pragma unroll
            for (int nf = 0; nf < 8; nf++) {
                int gj = nf * 8 + qc * 2;
                if (gj     > gi_lo) sacc[nf][0] = -1e30f;
                if (gj + 1 > gi_lo) sacc[nf][1] = -1e30f;
                if (gj     > gi_hi) sacc[nf][2] = -1e30f;
                if (gj + 1 > gi_hi) sacc[nf][3] = -1e30f;
            }
        }

        // ---- online softmax ----
        float mx_lo = -1e30f, mx_hi = -1e30f;
        #pragma unroll
        for (int nf = 0; nf < 8; nf++) {
            mx_lo = fmaxf(mx_lo, fmaxf(sacc[nf][0], sacc[nf][1]));
            mx_hi = fmaxf(mx_hi, fmaxf(sacc[nf][2], sacc[nf][3]));
        }
        mx_lo = fmaxf(mx_lo, __shfl_xor_sync(0xffffffffu, mx_lo, 1));
        mx_lo = fmaxf(mx_lo, __shfl_xor_sync(0xffffffffu, mx_lo, 2));
        mx_hi = fmaxf(mx_hi, __shfl_xor_sync(0xffffffffu, mx_hi, 1));
        mx_hi = fmaxf(mx_hi, __shfl_xor_sync(0xffffffffu, mx_hi, 2));

        float mn_lo = fmaxf(m_lo, mx_lo);
        float mn_hi = fmaxf(m_hi, mx_hi);
        float so_lo = __expf(m_lo - mn_lo);
        float so_hi = __expf(m_hi - mn_hi);

        float sum_lo = 0.f, sum_hi = 0.f;
        #pragma unroll
        for (int nf = 0; nf < 8; nf++) {
            sacc[nf][0] = __expf(sacc[nf][0] - mn_lo); sum_lo += sacc[nf][0];
            sacc[nf][1] = __expf(sacc[nf][1] - mn_lo); sum_lo += sacc[nf][1];
            sacc[nf][2] = __expf(sacc[nf][2] - mn_hi); sum_hi += sacc[nf][2];
            sacc[nf][3] = __expf(sacc[nf][3] - mn_hi); sum_hi += sacc[nf][3];
        }
        sum_lo += __shfl_xor_sync(0xffffffffu, sum_lo, 1);
        sum_lo += __shfl_xor_sync(0xffffffffu, sum_lo, 2);
        sum_hi += __shfl_xor_sync(0xffffffffu, sum_hi, 1);
        sum_hi += __shfl_xor_sync(0xffffffffu, sum_hi, 2);

        l_lo = l_lo * so_lo + sum_lo;  m_lo = mn_lo;
        l_hi = l_hi * so_hi + sum_hi;  m_hi = mn_hi;

        #pragma unroll
        for (int nf = 0; nf < 8; nf++) {
            oacc[nf][0] *= so_lo; oacc[nf][1] *= so_lo;
            oacc[nf][2] *= so_hi; oacc[nf][3] *= so_hi;
        }

        // ---- write P to shared (warp-private rows; tf32-rounded) ----
        {
            int r_lo = wid * 16 + qr;
            #pragma unroll
            for (int nf = 0; nf < 8; nf++) {
                int c = nf * 8 + qc * 2;
                *(float2*)&Ps[r_lo * APS + c] =
                    make_float2(f2tf32(sacc[nf][0]), f2tf32(sacc[nf][1]));
                *(float2*)&Ps[(r_lo + 8) * APS + c] =
                    make_float2(f2tf32(sacc[nf][2]), f2tf32(sacc[nf][3]));
            }
        }
        __syncwarp();

        // ---- O += P @ V ----
        #pragma unroll
        for (int kk = 0; kk < 8; kk++) {
            const float* pr = &Ps[(wid * 16 + qr) * APS + kk * 8 + qc];
            uint32_t a0 = __float_as_uint(pr[0]);
            uint32_t a1 = __float_as_uint(pr[8 * APS]);
            uint32_t a2 = __float_as_uint(pr[4]);
            uint32_t a3 = __float_as_uint(pr[8 * APS + 4]);
            #pragma unroll
            for (int nf = 0; nf < 8; nf++) {
                int col = nf * 8 + qr;
                uint32_t b0 = __float_as_uint(Vs[(kk * 8 + qc) * AVS + col]);
                uint32_t b1 = __float_as_uint(Vs[(kk * 8 + 4 + qc) * AVS + col]);
                mma_tf32(oacc[nf], a0, a1, a2, a3, b0, b1);
            }
        }
        __syncthreads();  // protect Ks/Vs before next iteration's overwrite
    }

    // ---- epilogue ----
    float inv_lo = 1.f / l_lo;
    float inv_hi = 1.f / l_hi;
    {
        int r_lo = b * SEQ + i0 + wid * 16 + qr;
        float* o0 = ao + (size_t)r_lo * DIM_INNER + h * DHEAD + qc * 2;
        float* o1 = ao + (size_t)(r_lo + 8) * DIM_INNER + h * DHEAD + qc * 2;
        #pragma unroll
        for (int nf = 0; nf < 8; nf++) {
            *(float2*)(o0 + nf * 8) = make_float2(oacc[nf][0] * inv_lo, oacc[nf][1] * inv_lo);
            *(float2*)(o1 + nf * 8) = make_float2(oacc[nf][2] * inv_hi, oacc[nf][3] * inv_hi);
        }
    }
}

// ============================ Launch =========================================
extern "C" void kernel_launch(void* const* d_in, const int* in_sizes, int n_in,
                              void* d_out, int out_size) {
    const float* x     = (const float*)d_in[0];
    const float* rot   = (const float*)d_in[1];
    const float* gamma = (const float*)d_in[2];
    const float* Wq    = (const float*)d_in[3];
    const float* Wkv   = (const float*)d_in[4];
    const float* Wout  = (const float*)d_in[5];
    float* out = (float*)d_out;

    float *xn, *q, *kv, *ao;
    cudaGetSymbolAddress((void**)&xn, g_xn);
    cudaGetSymbolAddress((void**)&q,  g_q);
    cudaGetSymbolAddress((void**)&kv, g_kv);
    cudaGetSymbolAddress((void**)&ao, g_ao);

    // 1) RMSNorm
    rmsnorm_kernel<<<ROWS, 256>>>(x, gamma, xn);

    // 2) TF32 tensor-core projections
    tf32_gemm<<<dim3(DIM_INNER / TBN, ROWS / TBM), 256>>>(xn, Wq, q, ROWS, DIM_INNER, DIM);
    tf32_gemm<<<dim3(2 * DIM_INNER / TBN, ROWS / TBM), 256>>>(xn, Wkv, kv, ROWS, 2 * DIM_INNER, DIM);

    // 3) RoPE on q and k
    {
        int tot = ROWS * HEADS * 32;
        rope_kernel<<<(tot + 255) / 256, 256>>>(rot, q, kv);
    }

    // 4) causal flash attention on tensor cores
    cudaFuncSetAttribute(flash_mma_kernel,
                         cudaFuncAttributeMaxDynamicSharedMemorySize, FSMEM2);
    flash_mma_kernel<<<dim3(SEQ / 64, BATCH * HEADS), 128, FSMEM2>>>(q, kv, ao);

    // 5) out projection
    tf32_gemm<<<dim3(DIM / TBN, ROWS / TBM), 256>>>(ao, Wout, out, ROWS, DIM, DIM);
}

// round 7
// speedup vs baseline: 3.6488x; 1.2499x over previous
#include <cuda_runtime.h>
#include <math.h>
#include <stdint.h>

// Problem constants
#define BATCH 2
#define SEQ   2048
#define DIM   2048
#define HEADS 32
#define DHEAD 64
#define ROWS  (BATCH * SEQ)          // 4096
#define DIM_INNER (HEADS * DHEAD)    // 2048

// ---------------- Scratch (static device globals — allocation-free) ----------
__device__ float g_xn[ROWS * DIM];
__device__ float g_q [ROWS * DIM_INNER];
__device__ float g_kv[ROWS * 2 * DIM_INNER];
__device__ float g_ao[ROWS * DIM_INNER];
__device__ float g_wq  [DIM * DIM_INNER];       // tf32-rounded weight copies
__device__ float g_wkv [DIM * 2 * DIM_INNER];
__device__ float g_wout[DIM_INNER * DIM];

// ============================ helpers ========================================
__device__ __forceinline__ float f2tf32(float x) {
    uint32_t u;
    asm("cvt.rna.tf32.f32 %0, %1;" : "=r"(u) : "f"(x));
    return __uint_as_float(u);
}
__device__ __forceinline__ void mma_tf32(float d[4],
                                         uint32_t a0, uint32_t a1, uint32_t a2, uint32_t a3,
                                         uint32_t b0, uint32_t b1) {
    asm volatile(
        "mma.sync.aligned.m16n8k8.row.col.f32.tf32.tf32.f32 "
        "{%0,%1,%2,%3}, {%4,%5,%6,%7}, {%8,%9}, {%0,%1,%2,%3};"
        : "+f"(d[0]), "+f"(d[1]), "+f"(d[2]), "+f"(d[3])
        : "r"(a0), "r"(a1), "r"(a2), "r"(a3), "r"(b0), "r"(b1));
}
__device__ __forceinline__ void cp16(uint32_t dst, const void* src) {
    asm volatile("cp.async.cg.shared.global [%0], [%1], 16;"
                 :: "r"(dst), "l"(__cvta_generic_to_global(src)));
}
__device__ __forceinline__ void cp_commit() {
    asm volatile("cp.async.commit_group;");
}
template<int N> __device__ __forceinline__ void cp_wait() {
    asm volatile("cp.async.wait_group %0;" :: "n"(N));
}

// ============================ RMSNorm (rounded output) =======================
__global__ void rmsnorm_kernel(const float* __restrict__ x,
                               const float* __restrict__ gamma,
                               float* __restrict__ xn) {
    int row = blockIdx.x;
    const float* xr = x + (size_t)row * DIM;
    float ss = 0.f;
    for (int i = threadIdx.x; i < DIM; i += blockDim.x) {
        float v = xr[i];
        ss += v * v;
    }
    __shared__ float red[32];
    int lane = threadIdx.x & 31, wid = threadIdx.x >> 5;
    #pragma unroll
    for (int off = 16; off > 0; off >>= 1) ss += __shfl_xor_sync(0xffffffffu, ss, off);
    if (lane == 0) red[wid] = ss;
    __syncthreads();
    if (wid == 0) {
        float v = (lane < (blockDim.x >> 5)) ? red[lane] : 0.f;
        #pragma unroll
        for (int off = 16; off > 0; off >>= 1) v += __shfl_xor_sync(0xffffffffu, v, off);
        if (lane == 0) red[0] = v;
    }
    __syncthreads();
    float norm = sqrtf(red[0]);
    float s = sqrtf((float)DIM) / fmaxf(norm, 1e-12f);
    float* xo = xn + (size_t)row * DIM;
    for (int i = threadIdx.x; i < DIM; i += blockDim.x)
        xo[i] = f2tf32(xr[i] * s * gamma[i]);
}

// =================== weight rounding copy (tf32 RNA) =========================
__global__ void round_copy(const float4* __restrict__ src,
                           float4* __restrict__ dst, int n4) {
    int i = blockIdx.x * blockDim.x + threadIdx.x;
    if (i >= n4) return;
    float4 v = src[i];
    v.x = f2tf32(v.x); v.y = f2tf32(v.y); v.z = f2tf32(v.z); v.w = f2tf32(v.w);
    dst[i] = v;
}

// ================ TF32 GEMM v2 (cp.async double-buffered) ====================
// C[M,N] = A[M,K] @ B[K,N]; inputs already tf32-rounded.
#define TBM 128
#define TBN 128
#define TBK 32
#define ASTRIDE 36
#define BSTRIDE 132
#define GSST (TBM * ASTRIDE + TBK * BSTRIDE)          // floats per stage = 8832
#define GEMM_SMEM (2 * GSST * (int)sizeof(float))     // 70656 bytes

__global__ void __launch_bounds__(256, 2)
tf32_gemm2(const float* __restrict__ A, const float* __restrict__ B,
           float* __restrict__ C, int M, int N, int K) {
    extern __shared__ float smp[];
    const int tid  = threadIdx.x;
    const int wid  = tid >> 5;
    const int lane = tid & 31;
    const int wm = (wid >> 2) * 64;
    const int wn = (wid & 3) * 32;
    const int brow = blockIdx.y * TBM;
    const int bcol = blockIdx.x * TBN;

    const int ar = tid >> 3;          // 0..31 (A rows base, B k-rows)
    const int ac = (tid & 7) * 4;     // 0..28
    const float* Ap = A + (size_t)(brow + ar) * K + ac;
    const float* Bp = B + (size_t)ar * N + bcol + ac;

    const uint32_t smb = (uint32_t)__cvta_generic_to_shared(smp);

    float acc[16][4];
    #pragma unroll
    for (int i = 0; i < 16; i++)
        #pragma unroll
        for (int j = 0; j < 4; j++) acc[i][j] = 0.f;

    const int KT = K / TBK;

    // stage(kt, p): issue 8 cp.async for tile kt into buffer p
    #define GSTAGE(kt, p) do {                                                  \
        uint32_t as_ = smb + (uint32_t)((p) * GSST) * 4u;                       \
        uint32_t bs_ = as_ + TBM * ASTRIDE * 4u;                                \
        _Pragma("unroll")                                                       \
        for (int i_ = 0; i_ < 4; i_++)                                          \
            cp16(as_ + ((ar + 32 * i_) * ASTRIDE + ac) * 4u,                    \
                 Ap + (size_t)(kt) * TBK + (size_t)(32 * i_) * K);              \
        _Pragma("unroll")                                                       \
        for (int i_ = 0; i_ < 4; i_++)                                          \
            cp16(bs_ + (ar * BSTRIDE + ac + 32 * i_) * 4u,                      \
                 Bp + (size_t)(kt) * TBK * N + 32 * i_);                        \
    } while (0)

    GSTAGE(0, 0);
    cp_commit();

    for (int kt = 0; kt < KT; kt++) {
        if (kt + 1 < KT) {
            GSTAGE(kt + 1, (kt + 1) & 1);
            cp_commit();
            cp_wait<1>();
        } else {
            cp_wait<0>();
        }
        __syncthreads();

        const float* As_ = smp + (kt & 1) * GSST;
        const float* Bs_ = As_ + TBM * ASTRIDE;

        #pragma unroll
        for (int kk = 0; kk < TBK; kk += 8) {
            uint32_t afrag[4][4];
            #pragma unroll
            for (int mf = 0; mf < 4; mf++) {
                int r = wm + mf * 16 + (lane >> 2);
                int c = kk + (lane & 3);
                afrag[mf][0] = __float_as_uint(As_[r * ASTRIDE + c]);
                afrag[mf][1] = __float_as_uint(As_[(r + 8) * ASTRIDE + c]);
                afrag[mf][2] = __float_as_uint(As_[r * ASTRIDE + c + 4]);
                afrag[mf][3] = __float_as_uint(As_[(r + 8) * ASTRIDE + c + 4]);
            }
            #pragma unroll
            for (int nf = 0; nf < 4; nf++) {
                int col = wn + nf * 8 + (lane >> 2);
                int kr  = kk + (lane & 3);
                uint32_t b0 = __float_as_uint(Bs_[kr * BSTRIDE + col]);
                uint32_t b1 = __float_as_uint(Bs_[(kr + 4) * BSTRIDE + col]);
                #pragma unroll
                for (int mf = 0; mf < 4; mf++)
                    mma_tf32(acc[mf * 4 + nf], afrag[mf][0], afrag[mf][1],
                             afrag[mf][2], afrag[mf][3], b0, b1);
            }
        }
        __syncthreads();
    }

    #pragma unroll
    for (int mf = 0; mf < 4; mf++) {
        int row = brow + wm + mf * 16 + (lane >> 2);
        #pragma unroll
        for (int nf = 0; nf < 4; nf++) {
            int col = bcol + wn + nf * 8 + (lane & 3) * 2;
            float* c0 = C + (size_t)row * N + col;
            float* c1 = C + (size_t)(row + 8) * N + col;
            *(float2*)c0 = make_float2(acc[mf * 4 + nf][0], acc[mf * 4 + nf][1]);
            *(float2*)c1 = make_float2(acc[mf * 4 + nf][2], acc[mf * 4 + nf][3]);
        }
    }
}

// ===================== RoPE (rounds q, k; rounds v) ==========================
__global__ void rope_kernel2(const float* __restrict__ rot,
                             float* __restrict__ q, float* __restrict__ kv) {
    int idx = blockIdx.x * blockDim.x + threadIdx.x;
    const int TOT = ROWS * HEADS * 32;
    if (idx >= TOT) return;
    int d = idx & 31;
    int h = (idx >> 5) & 31;
    int m = idx >> 10;
    int n = m & (SEQ - 1);

    float r0 = rot[n * DHEAD + d];
    float r1 = rot[n * DHEAD + d + 32];
    float c0 = cosf(r0), s0 = sinf(r0);
    float c1 = cosf(r1), s1 = sinf(r1);

    float* qp = q + (size_t)m * DIM_INNER + h * DHEAD;
    float q0 = qp[d], q1 = qp[d + 32];
    qp[d]      = f2tf32(q0 * c0 - q1 * s0);
    qp[d + 32] = f2tf32(q1 * c1 + q0 * s1);

    float* kp = kv + (size_t)m * (2 * DIM_INNER) + h * DHEAD;
    float k0 = kp[d], k1 = kp[d + 32];
    kp[d]      = f2tf32(k0 * c0 - k1 * s0);
    kp[d + 32] = f2tf32(k1 * c1 + k0 * s1);

    // round V in place (tf32 pre-rounding for attention PV mma)
    float* vp = kp + DIM_INNER;
    vp[d]      = f2tf32(vp[d]);
    vp[d + 32] = f2tf32(vp[d + 32]);
}

// ============ Flash attention v2 (tf32 mma + cp.async pipelining) ============
// BM=BN=64, 4 warps (16 rows each). K double-buffered (prefetch during PV of
// previous block); V single-buffered (cp.async issued end of previous iter,
// latency hidden behind S + softmax).
#define FKS 68
#define FVS 72
#define FPS 68
#define FKTILE (64 * FKS)  // floats per K buffer
#define FL_SMEM ((2 * FKTILE + 64 * FVS + 64 * FPS) * (int)sizeof(float))  // 70656

__global__ void __launch_bounds__(128, 3)
flash2(const float* __restrict__ q, const float* __restrict__ kv,
       float* __restrict__ ao) {
    extern __shared__ float sm[];
    float* Vs = sm + 2 * FKTILE;
    float* Ps = Vs + 64 * FVS;
    const uint32_t smb = (uint32_t)__cvta_generic_to_shared(sm);
    const uint32_t vsb = smb + 2u * FKTILE * 4u;

    const int bh = blockIdx.y;
    const int b  = bh >> 5;
    const int h  = bh & 31;
    const int i0 = (gridDim.x - 1 - blockIdx.x) * 64;  // heavy tiles first
    const int nj = i0 >> 6;

    const int tid  = threadIdx.x;
    const int wid  = tid >> 5;
    const int lane = tid & 31;
    const int qr   = lane >> 2;   // 0..7
    const int qc   = lane & 3;    // 0..3

    const int srow = tid >> 4;         // 0..7
    const int scol = (tid & 15) * 4;   // 0..60
    const float* kvbase = kv + (size_t)(b * SEQ) * (2 * DIM_INNER) + h * DHEAD;

    #define STAGE_K(jb, p) do {                                                  \
        const float* kb_ = kvbase + (size_t)((jb) * 64) * (2 * DIM_INNER);       \
        uint32_t kd_ = smb + (uint32_t)((p) * FKTILE) * 4u;                      \
        _Pragma("unroll")                                                        \
        for (int it_ = 0; it_ < 8; it_++) {                                      \
            int r_ = srow + 8 * it_;                                             \
            cp16(kd_ + (r_ * FKS + scol) * 4u,                                   \
                 kb_ + (size_t)r_ * (2 * DIM_INNER) + scol);                     \
        }                                                                        \
    } while (0)

    #define STAGE_V(jb) do {                                                     \
        const float* vb_ = kvbase + (size_t)((jb) * 64) * (2 * DIM_INNER) + DIM_INNER; \
        _Pragma("unroll")                                                        \
        for (int it_ = 0; it_ < 8; it_++) {                                      \
            int r_ = srow + 8 * it_;                                             \
            cp16(vsb + (r_ * FVS + scol) * 4u,                                   \
                 vb_ + (size_t)r_ * (2 * DIM_INNER) + scol);                     \
        }                                                                        \
    } while (0)

    // ---- Q A-fragments (pre-rounded; *0.125 is exact) ----
    uint32_t qf[8][4];
    {
        const float* qb = q + (size_t)(b * SEQ + i0 + wid * 16) * DIM_INNER + h * DHEAD;
        #pragma unroll
        for (int kk = 0; kk < 8; kk++) {
            qf[kk][0] = __float_as_uint(qb[(size_t)qr * DIM_INNER + kk * 8 + qc] * 0.125f);
            qf[kk][1] = __float_as_uint(qb[(size_t)(qr + 8) * DIM_INNER + kk * 8 + qc] * 0.125f);
            qf[kk][2] = __float_as_uint(qb[(size_t)qr * DIM_INNER + kk * 8 + 4 + qc] * 0.125f);
            qf[kk][3] = __float_as_uint(qb[(size_t)(qr + 8) * DIM_INNER + kk * 8 + 4 + qc] * 0.125f);
        }
    }

    float oacc[8][4];
    #pragma unroll
    for (int i = 0; i < 8; i++)
        #pragma unroll
        for (int j = 0; j < 4; j++) oacc[i][j] = 0.f;
    float m_lo = -1e30f, m_hi = -1e30f, l_lo = 0.f, l_hi = 0.f;

    // prologue: preload K0, V0
    STAGE_K(0, 0); cp_commit();
    STAGE_V(0);    cp_commit();

    for (int jb = 0; jb <= nj; jb++) {
        const int p = jb & 1;
        const bool hn = (jb < nj);

        if (hn) { STAGE_K(jb + 1, p ^ 1); cp_commit(); }
        if (hn) cp_wait<2>(); else cp_wait<1>();
        __syncthreads();                         // K(jb) visible everywhere

        const float* Ks = sm + p * FKTILE;

        // ---- S = Q @ K^T ----
        float sacc[8][4];
        #pragma unroll
        for (int i = 0; i < 8; i++)
            #pragma unroll
            for (int j = 0; j < 4; j++) sacc[i][j] = 0.f;

        #pragma unroll
        for (int kk = 0; kk < 8; kk++) {
            #pragma unroll
            for (int nf = 0; nf < 8; nf++) {
                int col = nf * 8 + qr;
                uint32_t b0 = __float_as_uint(Ks[col * FKS + kk * 8 + qc]);
                uint32_t b1 = __float_as_uint(Ks[col * FKS + kk * 8 + 4 + qc]);
                mma_tf32(sacc[nf], qf[kk][0], qf[kk][1], qf[kk][2], qf[kk][3], b0, b1);
            }
        }

        // ---- causal mask (diagonal block only) ----
        if (jb == nj) {
            int gi_lo = wid * 16 + qr;
            int gi_hi = gi_lo + 8;
            #pragma unroll
            for (int nf = 0; nf < 8; nf++) {
                int gj = nf * 8 + qc * 2;
                if (gj     > gi_lo) sacc[nf][0] = -1e30f;
                if (gj + 1 > gi_lo) sacc[nf][1] = -1e30f;
                if (gj     > gi_hi) sacc[nf][2] = -1e30f;
                if (gj + 1 > gi_hi) sacc[nf][3] = -1e30f;
            }
        }

        // ---- online softmax ----
        float mx_lo = -1e30f, mx_hi = -1e30f;
        #pragma unroll
        for (int nf = 0; nf < 8; nf++) {
            mx_lo = fmaxf(mx_lo, fmaxf(sacc[nf][0], sacc[nf][1]));
            mx_hi = fmaxf(mx_hi, fmaxf(sacc[nf][2], sacc[nf][3]));
        }
        mx_lo = fmaxf(mx_lo, __shfl_xor_sync(0xffffffffu, mx_lo, 1));
        mx_lo = fmaxf(mx_lo, __shfl_xor_sync(0xffffffffu, mx_lo, 2));
        mx_hi = fmaxf(mx_hi, __shfl_xor_sync(0xffffffffu, mx_hi, 1));
        mx_hi = fmaxf(mx_hi, __shfl_xor_sync(0xffffffffu, mx_hi, 2));

        float mn_lo = fmaxf(m_lo, mx_lo);
        float mn_hi = fmaxf(m_hi, mx_hi);
        float so_lo = __expf(m_lo - mn_lo);
        float so_hi = __expf(m_hi - mn_hi);

        float sum_lo = 0.f, sum_hi = 0.f;
        #pragma unroll
        for (int nf = 0; nf < 8; nf++) {
            sacc[nf][0] = __expf(sacc[nf][0] - mn_lo); sum_lo += sacc[nf][0];
            sacc[nf][1] = __expf(sacc[nf][1] - mn_lo); sum_lo += sacc[nf][1];
            sacc[nf][2] = __expf(sacc[nf][2] - mn_hi); sum_hi += sacc[nf][2];
            sacc[nf][3] = __expf(sacc[nf][3] - mn_hi); sum_hi += sacc[nf][3];
        }
        sum_lo += __shfl_xor_sync(0xffffffffu, sum_lo, 1);
        sum_lo += __shfl_xor_sync(0xffffffffu, sum_lo, 2);
        sum_hi += __shfl_xor_sync(0xffffffffu, sum_hi, 1);
        sum_hi += __shfl_xor_sync(0xffffffffu, sum_hi, 2);

        l_lo = l_lo * so_lo + sum_lo;  m_lo = mn_lo;
        l_hi = l_hi * so_hi + sum_hi;  m_hi = mn_hi;

        #pragma unroll
        for (int nf = 0; nf < 8; nf++) {
            oacc[nf][0] *= so_lo; oacc[nf][1] *= so_lo;
            oacc[nf][2] *= so_hi; oacc[nf][3] *= so_hi;
        }

        // ---- write P (RNA-rounded) to shared ----
        {
            int r_lo = wid * 16 + qr;
            #pragma unroll
            for (int nf = 0; nf < 8; nf++) {
                int c = nf * 8 + qc * 2;
                *(float2*)&Ps[r_lo * FPS + c] =
                    make_float2(f2tf32(sacc[nf][0]), f2tf32(sacc[nf][1]));
                *(float2*)&Ps[(r_lo + 8) * FPS + c] =
                    make_float2(f2tf32(sacc[nf][2]), f2tf32(sacc[nf][3]));
            }
        }

        if (hn) cp_wait<1>(); else cp_wait<0>();
        __syncthreads();                         // V(jb) + P visible

        // ---- O += P @ V ----
        #pragma unroll
        for (int kk = 0; kk < 8; kk++) {
            const float* pr = &Ps[(wid * 16 + qr) * FPS + kk * 8 + qc];
            uint32_t a0 = __float_as_uint(pr[0]);
            uint32_t a1 = __float_as_uint(pr[8 * FPS]);
            uint32_t a2 = __float_as_uint(pr[4]);
            uint32_t a3 = __float_as_uint(pr[8 * FPS + 4]);
            #pragma unroll
            for (int nf = 0; nf < 8; nf++) {
                int col = nf * 8 + qr;
                uint32_t b0 = __float_as_uint(Vs[(kk * 8 + qc) * FVS + col]);
                uint32_t b1 = __float_as_uint(Vs[(kk * 8 + 4 + qc) * FVS + col]);
                mma_tf32(oacc[nf], a0, a1, a2, a3, b0, b1);
            }
        }
        __syncthreads();                         // all warps done with Vs/Ps

        if (hn) { STAGE_V(jb + 1); cp_commit(); }
    }

    // ---- epilogue: normalize, round (feeds out-proj), store ----
    float inv_lo = 1.f / l_lo;
    float inv_hi = 1.f / l_hi;
    {
        int r_lo = b * SEQ + i0 + wid * 16 + qr;
        float* o0 = ao + (size_t)r_lo * DIM_INNER + h * DHEAD + qc * 2;
        float* o1 = ao + (size_t)(r_lo + 8) * DIM_INNER + h * DHEAD + qc * 2;
        #pragma unroll
        for (int nf = 0; nf < 8; nf++) {
            *(float2*)(o0 + nf * 8) = make_float2(f2tf32(oacc[nf][0] * inv_lo),
                                                  f2tf32(oacc[nf][1] * inv_lo));
            *(float2*)(o1 + nf * 8) = make_float2(f2tf32(oacc[nf][2] * inv_hi),
                                                  f2tf32(oacc[nf][3] * inv_hi));
        }
    }
}

// ============================ Launch =========================================
extern "C" void kernel_launch(void* const* d_in, const int* in_sizes, int n_in,
                              void* d_out, int out_size) {
    const float* x     = (const float*)d_in[0];
    const float* rot   = (const float*)d_in[1];
    const float* gamma = (const float*)d_in[2];
    const float* Wq    = (const float*)d_in[3];
    const float* Wkv   = (const float*)d_in[4];
    const float* Wout  = (const float*)d_in[5];
    float* out = (float*)d_out;

    float *xn, *q, *kv, *ao, *wq, *wkv, *wout;
    cudaGetSymbolAddress((void**)&xn,   g_xn);
    cudaGetSymbolAddress((void**)&q,    g_q);
    cudaGetSymbolAddress((void**)&kv,   g_kv);
    cudaGetSymbolAddress((void**)&ao,   g_ao);
    cudaGetSymbolAddress((void**)&wq,   g_wq);
    cudaGetSymbolAddress((void**)&wkv,  g_wkv);
    cudaGetSymbolAddress((void**)&wout, g_wout);

    cudaFuncSetAttribute(tf32_gemm2,
                         cudaFuncAttributeMaxDynamicSharedMemorySize, GEMM_SMEM);
    cudaFuncSetAttribute(flash2,
                         cudaFuncAttributeMaxDynamicSharedMemorySize, FL_SMEM);

    // 0) tf32-rounded weight copies
    {
        int n4q = DIM * DIM_INNER / 4;
        round_copy<<<(n4q + 255) / 256, 256>>>((const float4*)Wq,  (float4*)wq,  n4q);
        int n4kv = DIM * 2 * DIM_INNER / 4;
        round_copy<<<(n4kv + 255) / 256, 256>>>((const float4*)Wkv, (float4*)wkv, n4kv);
        int n4o = DIM_INNER * DIM / 4;
        round_copy<<<(n4o + 255) / 256, 256>>>((const float4*)Wout, (float4*)wout, n4o);
    }

    // 1) RMSNorm (tf32-rounded output)
    rmsnorm_kernel<<<ROWS, 256>>>(x, gamma, xn);

    // 2) projections (cp.async tf32 GEMM)
    tf32_gemm2<<<dim3(DIM_INNER / TBN, ROWS / TBM), 256, GEMM_SMEM>>>(
        xn, wq, q, ROWS, DIM_INNER, DIM);
    tf32_gemm2<<<dim3(2 * DIM_INNER / TBN, ROWS / TBM), 256, GEMM_SMEM>>>(
        xn, wkv, kv, ROWS, 2 * DIM_INNER, DIM);

    // 3) RoPE (+rounds q, k, v)
    {
        int tot = ROWS * HEADS * 32;
        rope_kernel2<<<(tot + 255) / 256, 256>>>(rot, q, kv);
    }

    // 4) causal flash attention (pipelined tf32 mma)
    flash2<<<dim3(SEQ / 64, BATCH * HEADS), 128, FL_SMEM>>>(q, kv, ao);

    // 5) out projection (raw fp32 output)
    tf32_gemm2<<<dim3(DIM / TBN, ROWS / TBM), 256, GEMM_SMEM>>>(
        ao, wout, out, ROWS, DIM, DIM);
}